// round 1
// baseline (speedup 1.0000x reference)
#include <cuda_runtime.h>
#include <math.h>

#define BB 2
#define LL 2048
#define DMD 1024
#define EE 2048
#define NS 16
#define KC 4
#define RR 64
#define MM (BB*LL)          // 4096
#define NCH 16
#define CLEN (LL/NCH)       // 128
#define FDIM (RR + 2*NS)    // 96

// ---------------- scratch (static device globals; no runtime alloc) ----------------
__device__ float g_xn[MM*DMD];          // 16 MB
__device__ float g_xz[MM*2*EE];         // 64 MB  (cols [0,E)=u, [E,2E)=z)
__device__ float g_uact[MM*EE];         // 32 MB
__device__ float g_xdbl[MM*FDIM];       // 1.5 MB
__device__ float g_dt[MM*EE];           // 32 MB
__device__ float g_ygate[MM*EE];        // 32 MB
__device__ float g_hend[BB*NCH*EE*NS];  // 4 MB
__device__ float g_hinit[BB*NCH*EE*NS]; // 4 MB
__device__ float g_sumdt[BB*NCH*EE];    // 256 KB

// ---------------- RMSNorm ----------------
__global__ void rmsnorm_kernel(const float* __restrict__ x, const float* __restrict__ w) {
    int row = blockIdx.x;
    int tid = threadIdx.x;
    const float4* xr = (const float4*)(x + (size_t)row * DMD);
    float4 v = xr[tid];
    float ss = v.x*v.x + v.y*v.y + v.z*v.z + v.w*v.w;
    __shared__ float red[8];
    #pragma unroll
    for (int o = 16; o > 0; o >>= 1) ss += __shfl_xor_sync(0xffffffffu, ss, o);
    if ((tid & 31) == 0) red[tid >> 5] = ss;
    __syncthreads();
    if (tid < 8) {
        float t = red[tid];
        #pragma unroll
        for (int o = 4; o > 0; o >>= 1) t += __shfl_xor_sync(0xffu, t, o, 8);
        if (tid == 0) red[0] = t;
    }
    __syncthreads();
    float scale = rsqrtf(red[0] * (1.0f / DMD) + 1e-5f);
    float4 wv = ((const float4*)w)[tid];
    float4 o4;
    o4.x = v.x * scale * wv.x;
    o4.y = v.y * scale * wv.y;
    o4.z = v.z * scale * wv.z;
    o4.w = v.w * scale * wv.w;
    ((float4*)(g_xn + (size_t)row * DMD))[tid] = o4;
}

// ---------------- generic TN SGEMM: C[M,N] = A[M,K] * B[N,K]^T ----------------
// BM=BN=128, BK=16, 256 threads, 8x8 per thread.
// EPI: 0=none, 1=softplus(c + bias[col]), 2=c + res[row*ldc+col]
template <int EPI>
__global__ __launch_bounds__(256) void sgemm_tn(
    const float* __restrict__ A, int lda,
    const float* __restrict__ B, int ldb,
    float* __restrict__ C, int ldc, int K,
    const float* __restrict__ aux)
{
    __shared__ float As[16][128];
    __shared__ float Bs[16][128];
    int tid = threadIdx.x;
    int m0 = blockIdx.y * 128;
    int n0 = blockIdx.x * 128;
    int lr = tid >> 2;          // 0..63
    int lk = (tid & 3) << 2;    // 0,4,8,12
    const float* Ap = A + (size_t)(m0 + lr) * lda + lk;
    const float* Bp = B + (size_t)(n0 + lr) * ldb + lk;
    int trow = (tid >> 4) << 3;
    int tcol = (tid & 15) << 3;

    float acc[8][8];
    #pragma unroll
    for (int i = 0; i < 8; i++)
        #pragma unroll
        for (int j = 0; j < 8; j++) acc[i][j] = 0.f;

    for (int kt = 0; kt < K; kt += 16) {
        float4 a0 = *(const float4*)(Ap + kt);
        float4 a1 = *(const float4*)(Ap + (size_t)64 * lda + kt);
        float4 b0 = *(const float4*)(Bp + kt);
        float4 b1 = *(const float4*)(Bp + (size_t)64 * ldb + kt);
        __syncthreads();
        As[lk+0][lr] = a0.x; As[lk+1][lr] = a0.y; As[lk+2][lr] = a0.z; As[lk+3][lr] = a0.w;
        As[lk+0][lr+64] = a1.x; As[lk+1][lr+64] = a1.y; As[lk+2][lr+64] = a1.z; As[lk+3][lr+64] = a1.w;
        Bs[lk+0][lr] = b0.x; Bs[lk+1][lr] = b0.y; Bs[lk+2][lr] = b0.z; Bs[lk+3][lr] = b0.w;
        Bs[lk+0][lr+64] = b1.x; Bs[lk+1][lr+64] = b1.y; Bs[lk+2][lr+64] = b1.z; Bs[lk+3][lr+64] = b1.w;
        __syncthreads();
        #pragma unroll
        for (int kk = 0; kk < 16; kk++) {
            float ra[8], rb[8];
            *(float4*)(ra)   = *(const float4*)&As[kk][trow];
            *(float4*)(ra+4) = *(const float4*)&As[kk][trow+4];
            *(float4*)(rb)   = *(const float4*)&Bs[kk][tcol];
            *(float4*)(rb+4) = *(const float4*)&Bs[kk][tcol+4];
            #pragma unroll
            for (int i = 0; i < 8; i++)
                #pragma unroll
                for (int j = 0; j < 8; j++)
                    acc[i][j] += ra[i] * rb[j];
        }
    }

    #pragma unroll
    for (int i = 0; i < 8; i++) {
        int row = m0 + trow + i;
        #pragma unroll
        for (int j = 0; j < 8; j++) {
            int col = n0 + tcol + j;
            float v = acc[i][j];
            if (EPI == 1) {
                v += aux[col];
                v = (v > 20.f) ? v : log1pf(expf(v));
            }
            if (EPI == 2) {
                v += aux[(size_t)row * ldc + col];
            }
            C[(size_t)row * ldc + col] = v;
        }
    }
}

// ---------------- causal depthwise conv (K=4) + SiLU ----------------
__global__ void conv_silu_kernel(const float* __restrict__ cw, const float* __restrict__ cb) {
    int idx = blockIdx.x * blockDim.x + threadIdx.x;  // over MM * (EE/4)
    const int ecnt = EE / 4;
    if (idx >= MM * ecnt) return;
    int e4 = idx % ecnt;
    int row = idx / ecnt;
    int l = row % LL;
    int e0 = e4 * 4;

    float wa[4][4];
    #pragma unroll
    for (int i = 0; i < 4; i++) {
        float4 wv = ((const float4*)cw)[e0 + i];
        wa[i][0] = wv.x; wa[i][1] = wv.y; wa[i][2] = wv.z; wa[i][3] = wv.w;
    }
    float4 acc = ((const float4*)cb)[e4];
    const float* up = g_xz + (size_t)row * (2*EE) + e0;
    #pragma unroll
    for (int j = 0; j < 4; j++) {
        int ls = l - 3 + j;
        if (ls >= 0) {
            float4 u = *(const float4*)(up + (ptrdiff_t)(j - 3) * (2*EE));
            acc.x += u.x * wa[0][j];
            acc.y += u.y * wa[1][j];
            acc.z += u.z * wa[2][j];
            acc.w += u.w * wa[3][j];
        }
    }
    float4 r;
    r.x = acc.x / (1.f + __expf(-acc.x));
    r.y = acc.y / (1.f + __expf(-acc.y));
    r.z = acc.z / (1.f + __expf(-acc.z));
    r.w = acc.w / (1.f + __expf(-acc.w));
    *(float4*)(g_uact + (size_t)row * EE + e0) = r;
}

// ---------------- x_proj: x_dbl[row,f] = dot(u_act[row,:], W[f,:]) ----------------
__global__ void xproj_kernel(const float* __restrict__ W) {
    __shared__ float su[EE];
    int row = blockIdx.x;
    const float4* ur = (const float4*)(g_uact + (size_t)row * EE);
    for (int i = threadIdx.x; i < EE/4; i += blockDim.x)
        ((float4*)su)[i] = ur[i];
    __syncthreads();
    if (threadIdx.x < FDIM) {
        const float4* w4 = (const float4*)(W + (size_t)threadIdx.x * EE);
        float a0 = 0.f, a1 = 0.f, a2 = 0.f, a3 = 0.f;
        #pragma unroll 4
        for (int k = 0; k < EE/4; k++) {
            float4 wv = w4[k];
            float4 uv = ((const float4*)su)[k];
            a0 += uv.x * wv.x; a1 += uv.y * wv.y;
            a2 += uv.z * wv.z; a3 += uv.w * wv.w;
        }
        g_xdbl[(size_t)row * FDIM + threadIdx.x] = (a0 + a1) + (a2 + a3);
    }
}

// ---------------- chunked selective scan ----------------
// pass 0: chunk-local scan from h=0, record h_end and sum(dt)
// pass 1: rescan with h_init, produce gated output (y + u*D)*silu(z)
__global__ void scan_pass_kernel(const float* __restrict__ A_log,
                                 const float* __restrict__ Dvec,
                                 int pass) {
    int e = blockIdx.x * 128 + threadIdx.x;
    int chunk = blockIdx.y;
    int b = blockIdx.z;

    float A[NS];
    #pragma unroll
    for (int n = 0; n < NS; n++) A[n] = -expf(A_log[e * NS + n]);

    int hbase = ((b * NCH + chunk) * EE + e) * NS;
    float h[NS];
    if (pass) {
        #pragma unroll
        for (int n = 0; n < NS; n++) h[n] = g_hinit[hbase + n];
    } else {
        #pragma unroll
        for (int n = 0; n < NS; n++) h[n] = 0.f;
    }
    float Dval = pass ? Dvec[e] : 0.f;
    float sdt = 0.f;

    __shared__ float sB[2][NS], sC[2][NS];

    for (int i = 0; i < CLEN; i++) {
        int l = chunk * CLEN + i;
        int row = b * LL + l;
        int s = i & 1;
        if (threadIdx.x < 2 * NS) {
            float v = g_xdbl[(size_t)row * FDIM + RR + threadIdx.x];
            if (threadIdx.x < NS) sB[s][threadIdx.x] = v;
            else                  sC[s][threadIdx.x - NS] = v;
        }
        __syncthreads();
        float dtv = g_dt[(size_t)row * EE + e];
        float uv  = g_uact[(size_t)row * EE + e];
        sdt += dtv;
        float du = dtv * uv;
        if (pass) {
            float y = 0.f;
            #pragma unroll
            for (int n = 0; n < NS; n++) {
                float dA = __expf(dtv * A[n]);
                h[n] = h[n] * dA + du * sB[s][n];
                y += h[n] * sC[s][n];
            }
            float z = g_xz[(size_t)row * (2*EE) + EE + e];
            float sig = 1.f / (1.f + __expf(-z));
            g_ygate[(size_t)row * EE + e] = (y + uv * Dval) * (z * sig);
        } else {
            #pragma unroll
            for (int n = 0; n < NS; n++) {
                float dA = __expf(dtv * A[n]);
                h[n] = h[n] * dA + du * sB[s][n];
            }
        }
    }
    if (!pass) {
        #pragma unroll
        for (int n = 0; n < NS; n++) g_hend[hbase + n] = h[n];
        g_sumdt[(b * NCH + chunk) * EE + e] = sdt;
    }
}

__global__ void scan_combine_kernel(const float* __restrict__ A_log) {
    int idx = blockIdx.x * blockDim.x + threadIdx.x;  // B*E
    if (idx >= BB * EE) return;
    int e = idx % EE;
    int b = idx / EE;
    float A[NS];
    #pragma unroll
    for (int n = 0; n < NS; n++) A[n] = -expf(A_log[e * NS + n]);
    float H[NS];
    #pragma unroll
    for (int n = 0; n < NS; n++) H[n] = 0.f;
    for (int c = 0; c < NCH; c++) {
        int base = ((b * NCH + c) * EE + e) * NS;
        #pragma unroll
        for (int n = 0; n < NS; n++) g_hinit[base + n] = H[n];
        float s = g_sumdt[(b * NCH + c) * EE + e];
        #pragma unroll
        for (int n = 0; n < NS; n++)
            H[n] = g_hend[base + n] + __expf(A[n] * s) * H[n];
    }
}

// ---------------- launch ----------------
extern "C" void kernel_launch(void* const* d_in, const int* in_sizes, int n_in,
                              void* d_out, int out_size) {
    const float* x         = (const float*)d_in[0];
    const float* norm_w    = (const float*)d_in[1];
    const float* in_proj_w = (const float*)d_in[2];
    const float* conv_w    = (const float*)d_in[3];
    const float* conv_b    = (const float*)d_in[4];
    const float* x_proj_w  = (const float*)d_in[5];
    const float* dt_proj_w = (const float*)d_in[6];
    const float* dt_proj_b = (const float*)d_in[7];
    const float* A_log     = (const float*)d_in[8];
    const float* Dvec      = (const float*)d_in[9];
    const float* out_proj_w= (const float*)d_in[10];
    float* out = (float*)d_out;

    float *p_xn, *p_xz, *p_xdbl, *p_dt, *p_ygate;
    cudaGetSymbolAddress((void**)&p_xn, g_xn);
    cudaGetSymbolAddress((void**)&p_xz, g_xz);
    cudaGetSymbolAddress((void**)&p_xdbl, g_xdbl);
    cudaGetSymbolAddress((void**)&p_dt, g_dt);
    cudaGetSymbolAddress((void**)&p_ygate, g_ygate);

    // 1. RMSNorm
    rmsnorm_kernel<<<MM, 256>>>(x, norm_w);
    // 2. in_proj: xz[4096, 4096] = xn[4096,1024] @ W[4096,1024]^T
    sgemm_tn<0><<<dim3(2*EE/128, MM/128), 256>>>(p_xn, DMD, in_proj_w, DMD, p_xz, 2*EE, DMD, nullptr);
    // 3. causal depthwise conv + SiLU -> u_act
    conv_silu_kernel<<<(MM * (EE/4)) / 256, 256>>>(conv_w, conv_b);
    // 4. x_proj -> x_dbl[4096, 96]
    xproj_kernel<<<MM, 128>>>(x_proj_w);
    // 5. dt = softplus(dt_low @ dtW^T + b): A=x_dbl cols [0,64), lda=96
    sgemm_tn<1><<<dim3(EE/128, MM/128), 256>>>(p_xdbl, FDIM, dt_proj_w, RR, p_dt, EE, RR, dt_proj_b);
    // 6-8. chunked selective scan + fused gate
    scan_pass_kernel<<<dim3(EE/128, NCH, BB), 128>>>(A_log, Dvec, 0);
    scan_combine_kernel<<<(BB*EE)/256, 256>>>(A_log);
    scan_pass_kernel<<<dim3(EE/128, NCH, BB), 128>>>(A_log, Dvec, 1);
    // 9. out_proj + residual: out[4096,1024] = ygate @ Wout^T + x
    sgemm_tn<2><<<dim3(DMD/128, MM/128), 256>>>(p_ygate, EE, out_proj_w, EE, out, DMD, EE, x);
}

// round 3
// speedup vs baseline: 1.3843x; 1.3843x over previous
#include <cuda_runtime.h>
#include <math.h>

#define BB 2
#define LL 2048
#define DMD 1024
#define EE 2048
#define NS 16
#define KC 4
#define RR 64
#define MM (BB*LL)          // 4096
#define NCH 16
#define CLEN (LL/NCH)       // 128
#define FDIM (RR + 2*NS)    // 96
#define XKS 4               // split-K factor for x_proj

// ---------------- scratch (static device globals; no runtime alloc) ----------------
__device__ float g_xn[MM*DMD];          // 16 MB
__device__ float g_xz[MM*2*EE];         // 64 MB  (cols [0,E)=u, [E,2E)=z)
__device__ float g_uact[MM*EE];         // 32 MB
__device__ float g_xdbl[MM*FDIM];       // 1.5 MB
__device__ float g_xpart[XKS*MM*FDIM];  // 6.3 MB
__device__ float g_dt[MM*EE];           // 32 MB
__device__ float g_ygate[MM*EE];        // 32 MB
__device__ float g_hend[BB*NCH*EE*NS];  // 4 MB
__device__ float g_hinit[BB*NCH*EE*NS]; // 4 MB
__device__ float g_sumdt[BB*NCH*EE];    // 256 KB

// ---------------- RMSNorm ----------------
__global__ void rmsnorm_kernel(const float* __restrict__ x, const float* __restrict__ w) {
    int row = blockIdx.x;
    int tid = threadIdx.x;
    const float4* xr = (const float4*)(x + (size_t)row * DMD);
    float4 v = xr[tid];
    float ss = v.x*v.x + v.y*v.y + v.z*v.z + v.w*v.w;
    __shared__ float red[8];
    #pragma unroll
    for (int o = 16; o > 0; o >>= 1) ss += __shfl_xor_sync(0xffffffffu, ss, o);
    if ((tid & 31) == 0) red[tid >> 5] = ss;
    __syncthreads();
    if (tid < 8) {
        float t = red[tid];
        #pragma unroll
        for (int o = 4; o > 0; o >>= 1) t += __shfl_xor_sync(0xffu, t, o, 8);
        if (tid == 0) red[0] = t;
    }
    __syncthreads();
    float scale = rsqrtf(red[0] * (1.0f / DMD) + 1e-5f);
    float4 wv = ((const float4*)w)[tid];
    float4 o4;
    o4.x = v.x * scale * wv.x;
    o4.y = v.y * scale * wv.y;
    o4.z = v.z * scale * wv.z;
    o4.w = v.w * scale * wv.w;
    ((float4*)(g_xn + (size_t)row * DMD))[tid] = o4;
}

// ---------------- generic TN SGEMM: C[M,N] = A[M,K] * B[N,K]^T ----------------
// BM=BN=128, BK=16, 256 threads, 8x8 per thread.
// EPI: 0=none, 1=softplus(c + bias[col]), 2=c + res[row*ldc+col]
template <int EPI>
__global__ __launch_bounds__(256) void sgemm_tn(
    const float* __restrict__ A, int lda,
    const float* __restrict__ B, int ldb,
    float* __restrict__ C, int ldc, int K,
    const float* __restrict__ aux)
{
    __shared__ float As[16][128];
    __shared__ float Bs[16][128];
    int tid = threadIdx.x;
    int m0 = blockIdx.y * 128;
    int n0 = blockIdx.x * 128;
    int lr = tid >> 2;          // 0..63
    int lk = (tid & 3) << 2;    // 0,4,8,12
    const float* Ap = A + (size_t)(m0 + lr) * lda + lk;
    const float* Bp = B + (size_t)(n0 + lr) * ldb + lk;
    int trow = (tid >> 4) << 3;
    int tcol = (tid & 15) << 3;

    float acc[8][8];
    #pragma unroll
    for (int i = 0; i < 8; i++)
        #pragma unroll
        for (int j = 0; j < 8; j++) acc[i][j] = 0.f;

    for (int kt = 0; kt < K; kt += 16) {
        float4 a0 = *(const float4*)(Ap + kt);
        float4 a1 = *(const float4*)(Ap + (size_t)64 * lda + kt);
        float4 b0 = *(const float4*)(Bp + kt);
        float4 b1 = *(const float4*)(Bp + (size_t)64 * ldb + kt);
        __syncthreads();
        As[lk+0][lr] = a0.x; As[lk+1][lr] = a0.y; As[lk+2][lr] = a0.z; As[lk+3][lr] = a0.w;
        As[lk+0][lr+64] = a1.x; As[lk+1][lr+64] = a1.y; As[lk+2][lr+64] = a1.z; As[lk+3][lr+64] = a1.w;
        Bs[lk+0][lr] = b0.x; Bs[lk+1][lr] = b0.y; Bs[lk+2][lr] = b0.z; Bs[lk+3][lr] = b0.w;
        Bs[lk+0][lr+64] = b1.x; Bs[lk+1][lr+64] = b1.y; Bs[lk+2][lr+64] = b1.z; Bs[lk+3][lr+64] = b1.w;
        __syncthreads();
        #pragma unroll
        for (int kk = 0; kk < 16; kk++) {
            float ra[8], rb[8];
            *(float4*)(ra)   = *(const float4*)&As[kk][trow];
            *(float4*)(ra+4) = *(const float4*)&As[kk][trow+4];
            *(float4*)(rb)   = *(const float4*)&Bs[kk][tcol];
            *(float4*)(rb+4) = *(const float4*)&Bs[kk][tcol+4];
            #pragma unroll
            for (int i = 0; i < 8; i++)
                #pragma unroll
                for (int j = 0; j < 8; j++)
                    acc[i][j] += ra[i] * rb[j];
        }
    }

    #pragma unroll
    for (int i = 0; i < 8; i++) {
        int row = m0 + trow + i;
        #pragma unroll
        for (int j = 0; j < 8; j++) {
            int col = n0 + tcol + j;
            float v = acc[i][j];
            if (EPI == 1) {
                v += aux[col];
                v = (v > 20.f) ? v : log1pf(expf(v));
            }
            if (EPI == 2) {
                v += aux[(size_t)row * ldc + col];
            }
            C[(size_t)row * ldc + col] = v;
        }
    }
}

// ---------------- causal depthwise conv (K=4) + SiLU ----------------
__global__ void conv_silu_kernel(const float* __restrict__ cw, const float* __restrict__ cb) {
    int idx = blockIdx.x * blockDim.x + threadIdx.x;  // over MM * (EE/4)
    const int ecnt = EE / 4;
    if (idx >= MM * ecnt) return;
    int e4 = idx % ecnt;
    int row = idx / ecnt;
    int l = row % LL;
    int e0 = e4 * 4;

    float wa[4][4];
    #pragma unroll
    for (int i = 0; i < 4; i++) {
        float4 wv = ((const float4*)cw)[e0 + i];
        wa[i][0] = wv.x; wa[i][1] = wv.y; wa[i][2] = wv.z; wa[i][3] = wv.w;
    }
    float4 acc = ((const float4*)cb)[e4];
    const float* up = g_xz + (size_t)row * (2*EE) + e0;
    #pragma unroll
    for (int j = 0; j < 4; j++) {
        int ls = l - 3 + j;
        if (ls >= 0) {
            float4 u = *(const float4*)(up + (ptrdiff_t)(j - 3) * (2*EE));
            acc.x += u.x * wa[0][j];
            acc.y += u.y * wa[1][j];
            acc.z += u.z * wa[2][j];
            acc.w += u.w * wa[3][j];
        }
    }
    float4 r;
    r.x = acc.x / (1.f + __expf(-acc.x));
    r.y = acc.y / (1.f + __expf(-acc.y));
    r.z = acc.z / (1.f + __expf(-acc.z));
    r.w = acc.w / (1.f + __expf(-acc.w));
    *(float4*)(g_uact + (size_t)row * EE + e0) = r;
}

// ---------------- x_proj split-K GEMM ----------------
// partial[s][row,f] = u_act[row, s*512:(s+1)*512] @ W[f, s*512:(s+1)*512]^T
// BM=128, BN=96 (full), BK=32, 256 threads, 8x6 microtile.
__global__ __launch_bounds__(256) void xproj_gemm(const float* __restrict__ W) {
    __shared__ float As[32][132];   // padded: odd-ish stride, 16B-aligned rows
    __shared__ float Bs[32][100];
    int tid = threadIdx.x;
    int m0 = blockIdx.x * 128;
    int k0 = blockIdx.y * (EE / XKS);
    int trow = (tid >> 4) << 3;     // 0..120
    int tcol = (tid & 15) * 6;      // 0..90

    float acc[8][6];
    #pragma unroll
    for (int i = 0; i < 8; i++)
        #pragma unroll
        for (int j = 0; j < 6; j++) acc[i][j] = 0.f;

    for (int kt = 0; kt < EE / XKS; kt += 32) {
        int kb = k0 + kt;
        __syncthreads();
        #pragma unroll
        for (int i = 0; i < 4; i++) {               // A: 128 rows x 8 float4
            int li = tid + i * 256;
            int row = li >> 3;
            int kq = (li & 7) << 2;
            float4 v = *(const float4*)(g_uact + (size_t)(m0 + row) * EE + kb + kq);
            As[kq+0][row] = v.x; As[kq+1][row] = v.y;
            As[kq+2][row] = v.z; As[kq+3][row] = v.w;
        }
        #pragma unroll
        for (int i = 0; i < 3; i++) {               // B: 96 rows x 8 float4
            int li = tid + i * 256;
            int row = li >> 3;
            int kq = (li & 7) << 2;
            float4 v = *(const float4*)(W + (size_t)row * EE + kb + kq);
            Bs[kq+0][row] = v.x; Bs[kq+1][row] = v.y;
            Bs[kq+2][row] = v.z; Bs[kq+3][row] = v.w;
        }
        __syncthreads();
        #pragma unroll
        for (int kk = 0; kk < 32; kk++) {
            float ra[8], rb[6];
            *(float4*)(ra)   = *(const float4*)&As[kk][trow];
            *(float4*)(ra+4) = *(const float4*)&As[kk][trow+4];
            *(float2*)(rb)   = *(const float2*)&Bs[kk][tcol];
            *(float2*)(rb+2) = *(const float2*)&Bs[kk][tcol+2];
            *(float2*)(rb+4) = *(const float2*)&Bs[kk][tcol+4];
            #pragma unroll
            for (int i = 0; i < 8; i++)
                #pragma unroll
                for (int j = 0; j < 6; j++)
                    acc[i][j] += ra[i] * rb[j];
        }
    }

    float* outp = g_xpart + (size_t)blockIdx.y * MM * FDIM;
    #pragma unroll
    for (int i = 0; i < 8; i++)
        #pragma unroll
        for (int j = 0; j < 6; j++)
            outp[(size_t)(m0 + trow + i) * FDIM + tcol + j] = acc[i][j];
}

__global__ void xproj_reduce() {
    int idx = blockIdx.x * 256 + threadIdx.x;
    if (idx >= MM * FDIM) return;
    float s = 0.f;
    #pragma unroll
    for (int p = 0; p < XKS; p++) s += g_xpart[(size_t)p * MM * FDIM + idx];
    g_xdbl[idx] = s;
}

// ---------------- chunked selective scan ----------------
__global__ void scan_pass_kernel(const float* __restrict__ A_log,
                                 const float* __restrict__ Dvec,
                                 int pass) {
    int e = blockIdx.x * 128 + threadIdx.x;
    int chunk = blockIdx.y;
    int b = blockIdx.z;

    float A[NS];
    #pragma unroll
    for (int n = 0; n < NS; n++) A[n] = -expf(A_log[e * NS + n]);

    int hbase = ((b * NCH + chunk) * EE + e) * NS;
    float h[NS];
    if (pass) {
        #pragma unroll
        for (int n = 0; n < NS; n++) h[n] = g_hinit[hbase + n];
    } else {
        #pragma unroll
        for (int n = 0; n < NS; n++) h[n] = 0.f;
    }
    float Dval = pass ? Dvec[e] : 0.f;
    float sdt = 0.f;

    __shared__ float sB[2][NS], sC[2][NS];

    for (int i = 0; i < CLEN; i++) {
        int l = chunk * CLEN + i;
        int row = b * LL + l;
        int s = i & 1;
        if (threadIdx.x < 2 * NS) {
            float v = g_xdbl[(size_t)row * FDIM + RR + threadIdx.x];
            if (threadIdx.x < NS) sB[s][threadIdx.x] = v;
            else                  sC[s][threadIdx.x - NS] = v;
        }
        __syncthreads();
        float dtv = g_dt[(size_t)row * EE + e];
        float uv  = g_uact[(size_t)row * EE + e];
        sdt += dtv;
        float du = dtv * uv;
        if (pass) {
            float y = 0.f;
            #pragma unroll
            for (int n = 0; n < NS; n++) {
                float dA = __expf(dtv * A[n]);
                h[n] = h[n] * dA + du * sB[s][n];
                y += h[n] * sC[s][n];
            }
            float z = g_xz[(size_t)row * (2*EE) + EE + e];
            float sig = 1.f / (1.f + __expf(-z));
            g_ygate[(size_t)row * EE + e] = (y + uv * Dval) * (z * sig);
        } else {
            #pragma unroll
            for (int n = 0; n < NS; n++) {
                float dA = __expf(dtv * A[n]);
                h[n] = h[n] * dA + du * sB[s][n];
            }
        }
    }
    if (!pass) {
        #pragma unroll
        for (int n = 0; n < NS; n++) g_hend[hbase + n] = h[n];
        g_sumdt[(b * NCH + chunk) * EE + e] = sdt;
    }
}

__global__ void scan_combine_kernel(const float* __restrict__ A_log) {
    int idx = blockIdx.x * blockDim.x + threadIdx.x;  // B*E
    if (idx >= BB * EE) return;
    int e = idx % EE;
    int b = idx / EE;
    float A[NS];
    #pragma unroll
    for (int n = 0; n < NS; n++) A[n] = -expf(A_log[e * NS + n]);
    float H[NS];
    #pragma unroll
    for (int n = 0; n < NS; n++) H[n] = 0.f;
    for (int c = 0; c < NCH; c++) {
        int base = ((b * NCH + c) * EE + e) * NS;
        #pragma unroll
        for (int n = 0; n < NS; n++) g_hinit[base + n] = H[n];
        float s = g_sumdt[(b * NCH + c) * EE + e];
        #pragma unroll
        for (int n = 0; n < NS; n++)
            H[n] = g_hend[base + n] + __expf(A[n] * s) * H[n];
    }
}

// ---------------- launch ----------------
extern "C" void kernel_launch(void* const* d_in, const int* in_sizes, int n_in,
                              void* d_out, int out_size) {
    const float* x         = (const float*)d_in[0];
    const float* norm_w    = (const float*)d_in[1];
    const float* in_proj_w = (const float*)d_in[2];
    const float* conv_w    = (const float*)d_in[3];
    const float* conv_b    = (const float*)d_in[4];
    const float* x_proj_w  = (const float*)d_in[5];
    const float* dt_proj_w = (const float*)d_in[6];
    const float* dt_proj_b = (const float*)d_in[7];
    const float* A_log     = (const float*)d_in[8];
    const float* Dvec      = (const float*)d_in[9];
    const float* out_proj_w= (const float*)d_in[10];
    float* out = (float*)d_out;

    float *p_xn, *p_xz, *p_xdbl, *p_dt, *p_ygate;
    cudaGetSymbolAddress((void**)&p_xn, g_xn);
    cudaGetSymbolAddress((void**)&p_xz, g_xz);
    cudaGetSymbolAddress((void**)&p_xdbl, g_xdbl);
    cudaGetSymbolAddress((void**)&p_dt, g_dt);
    cudaGetSymbolAddress((void**)&p_ygate, g_ygate);

    // 1. RMSNorm
    rmsnorm_kernel<<<MM, 256>>>(x, norm_w);
    // 2. in_proj: xz[4096, 4096] = xn[4096,1024] @ W[4096,1024]^T
    sgemm_tn<0><<<dim3(2*EE/128, MM/128), 256>>>(p_xn, DMD, in_proj_w, DMD, p_xz, 2*EE, DMD, nullptr);
    // 3. causal depthwise conv + SiLU -> u_act
    conv_silu_kernel<<<(MM * (EE/4)) / 256, 256>>>(conv_w, conv_b);
    // 4. x_proj -> x_dbl[4096, 96] (split-K GEMM + reduce)
    xproj_gemm<<<dim3(MM/128, XKS), 256>>>(x_proj_w);
    xproj_reduce<<<(MM*FDIM)/256, 256>>>();
    // 5. dt = softplus(dt_low @ dtW^T + b): A=x_dbl cols [0,64), lda=96
    sgemm_tn<1><<<dim3(EE/128, MM/128), 256>>>(p_xdbl, FDIM, dt_proj_w, RR, p_dt, EE, RR, dt_proj_b);
    // 6-8. chunked selective scan + fused gate
    scan_pass_kernel<<<dim3(EE/128, NCH, BB), 128>>>(A_log, Dvec, 0);
    scan_combine_kernel<<<(BB*EE)/256, 256>>>(A_log);
    scan_pass_kernel<<<dim3(EE/128, NCH, BB), 128>>>(A_log, Dvec, 1);
    // 9. out_proj + residual: out[4096,1024] = ygate @ Wout^T + x
    sgemm_tn<2><<<dim3(DMD/128, MM/128), 256>>>(p_ygate, EE, out_proj_w, EE, out, DMD, EE, x);
}

// round 7
// speedup vs baseline: 2.2521x; 1.6269x over previous
#include <cuda_runtime.h>
#include <cuda_bf16.h>
#include <math.h>
#include <stdint.h>

#define BB 2
#define LL 2048
#define DMD 1024
#define EE 2048
#define NS 16
#define RR 64
#define MM (BB*LL)          // 4096
#define NCH 16
#define CLEN (LL/NCH)       // 128
#define FDIM (RR + 2*NS)    // 96
#define XKS 4               // split-K factor for x_proj

// HMMA GEMM tiling
#define LDSROW 40           // bf16 elems per smem row (32 data + 8 pad) -> 80B stride
#define OPBYTES (128*LDSROW*2)   // 10240 per operand per stage
#define STAGE_BYTES (4*OPBYTES)  // Ah | Al | Bh | Bl
#define GSTAGES 3
#define DSMEM (GSTAGES*STAGE_BYTES)   // 122880

// ---------------- scratch (static device globals; no runtime alloc) ----------------
__device__ float g_xn[MM*DMD];
__device__ float g_xz[MM*2*EE];
__device__ float g_uact[MM*EE];
__device__ float g_xdbl[MM*FDIM];
__device__ float g_xpart[XKS*MM*FDIM];
__device__ float g_dt[MM*EE];
__device__ float g_ygate[MM*EE];
__device__ float g_hend[BB*NCH*EE*NS];
__device__ float g_hinit[BB*NCH*EE*NS];
__device__ float g_sumdt[BB*NCH*EE];
// bf16 hi/lo split operands (16B-aligned for cp.async/float4)
__device__ __align__(256) __nv_bfloat16 g_xn_h[MM*DMD];
__device__ __align__(256) __nv_bfloat16 g_xn_l[MM*DMD];
__device__ __align__(256) __nv_bfloat16 g_w1_h[2*EE*DMD];
__device__ __align__(256) __nv_bfloat16 g_w1_l[2*EE*DMD];
__device__ __align__(256) __nv_bfloat16 g_yg_h[MM*EE];
__device__ __align__(256) __nv_bfloat16 g_yg_l[MM*EE];
__device__ __align__(256) __nv_bfloat16 g_w2_h[DMD*EE];
__device__ __align__(256) __nv_bfloat16 g_w2_l[DMD*EE];

// ---------------- PTX helpers (sm_80-era ISA only; no tcgen05) ----------------
__device__ __forceinline__ uint32_t smem_u32(const void* p) {
    uint32_t a;
    asm("{ .reg .u64 t; cvta.to.shared.u64 t, %1; cvt.u32.u64 %0, t; }" : "=r"(a) : "l"(p));
    return a;
}
__device__ __forceinline__ void ldgsts16(uint32_t s, const void* g) {
    asm volatile("cp.async.cg.shared.global [%0], [%1], 16;" :: "r"(s), "l"(g));
}
__device__ __forceinline__ void cp_commit() {
    asm volatile("cp.async.commit_group;" ::: "memory");
}
__device__ __forceinline__ void cp_wait2() {
    asm volatile("cp.async.wait_group 2;" ::: "memory");
}
__device__ __forceinline__ void ldsm4(uint32_t a, uint32_t& r0, uint32_t& r1,
                                      uint32_t& r2, uint32_t& r3) {
    asm volatile("ldmatrix.sync.aligned.m8n8.x4.shared.b16 {%0,%1,%2,%3}, [%4];"
        : "=r"(r0), "=r"(r1), "=r"(r2), "=r"(r3) : "r"(a));
}
__device__ __forceinline__ void mma16816(float* c, const uint32_t* a, const uint32_t* b) {
    asm volatile(
        "mma.sync.aligned.m16n8k16.row.col.f32.bf16.bf16.f32 "
        "{%0,%1,%2,%3}, {%4,%5,%6,%7}, {%8,%9}, {%0,%1,%2,%3};"
        : "+f"(c[0]), "+f"(c[1]), "+f"(c[2]), "+f"(c[3])
        : "r"(a[0]), "r"(a[1]), "r"(a[2]), "r"(a[3]), "r"(b[0]), "r"(b[1]));
}

// ---------------- fp32 -> bf16 hi/lo split ----------------
__global__ void cvt_hilo(const float* __restrict__ src,
                         __nv_bfloat16* __restrict__ h,
                         __nv_bfloat16* __restrict__ l, int n4) {
    int i = blockIdx.x * 256 + threadIdx.x;
    if (i >= n4) return;
    float4 v = ((const float4*)src)[i];
    __nv_bfloat16 h0 = __float2bfloat16_rn(v.x), h1 = __float2bfloat16_rn(v.y);
    __nv_bfloat16 h2 = __float2bfloat16_rn(v.z), h3 = __float2bfloat16_rn(v.w);
    __nv_bfloat16 l0 = __float2bfloat16_rn(v.x - __bfloat162float(h0));
    __nv_bfloat16 l1 = __float2bfloat16_rn(v.y - __bfloat162float(h1));
    __nv_bfloat16 l2 = __float2bfloat16_rn(v.z - __bfloat162float(h2));
    __nv_bfloat16 l3 = __float2bfloat16_rn(v.w - __bfloat162float(h3));
    ((__nv_bfloat162*)h)[2*i]   = __nv_bfloat162(h0, h1);
    ((__nv_bfloat162*)h)[2*i+1] = __nv_bfloat162(h2, h3);
    ((__nv_bfloat162*)l)[2*i]   = __nv_bfloat162(l0, l1);
    ((__nv_bfloat162*)l)[2*i+1] = __nv_bfloat162(l2, l3);
}

// ---------------- split-bf16 HMMA GEMM: C[M,N] = A[M,K] * B[N,K]^T ----------------
// 128x128 CTA tile, 8 warps (2x4), 64x32 per warp, BK=32, 3-stage cp.async.
// D = Ah*Bh + Ah*Bl + Al*Bh accumulated in fp32. EPI: 0=store, 2=+res.
template <int KEL, int EPI>
__global__ void __launch_bounds__(256, 1) hmma_gemm(
    const __nv_bfloat16* __restrict__ Ah, const __nv_bfloat16* __restrict__ Al,
    const __nv_bfloat16* __restrict__ Bh, const __nv_bfloat16* __restrict__ Bl,
    float* __restrict__ C, int ldc, const float* __restrict__ res)
{
    constexpr int NC = KEL / 32;           // k-chunks
    extern __shared__ __align__(128) char dsm[];
    uint32_t base = smem_u32(dsm);

    int tid = threadIdx.x, lid = tid & 31, wid = tid >> 5;
    int wm = (wid & 1) * 64;               // warp row offset
    int wn = (wid >> 1) * 32;              // warp col offset
    int m0 = blockIdx.y * 128, n0 = blockIdx.x * 128;

    // cp.async geometry: thread -> (row, 2 of 4 16B segs)
    int grow = tid >> 1;
    int gseg = (tid & 1) * 2;
    const char* pAh = (const char*)(Ah + (size_t)m0 * KEL);
    const char* pAl = (const char*)(Al + (size_t)m0 * KEL);
    const char* pBh = (const char*)(Bh + (size_t)n0 * KEL);
    const char* pBl = (const char*)(Bl + (size_t)n0 * KEL);

    auto load_chunk = [&](int c) {
        uint32_t sb = base + (c % GSTAGES) * STAGE_BYTES;
        #pragma unroll
        for (int s2 = 0; s2 < 2; s2++) {
            int seg = gseg + s2;
            uint32_t so = grow * 80 + seg * 16;
            size_t go = (size_t)grow * (KEL * 2) + (size_t)c * 64 + seg * 16;
            ldgsts16(sb +             so, pAh + go);
            ldgsts16(sb + OPBYTES   + so, pAl + go);
            ldgsts16(sb + 2*OPBYTES + so, pBh + go);
            ldgsts16(sb + 3*OPBYTES + so, pBl + go);
        }
        cp_commit();
    };

    // per-lane ldmatrix offsets
    int quad = lid >> 3, r8 = lid & 7;
    uint32_t a_off = (uint32_t)((quad & 1) * 8 + r8) * 80 + (uint32_t)(quad >> 1) * 16;
    uint32_t b_off = (uint32_t)((quad >> 1) * 8 + r8) * 80 + (uint32_t)(quad & 1) * 16;

    float acc[4][4][4];
    #pragma unroll
    for (int i = 0; i < 4; i++)
        #pragma unroll
        for (int j = 0; j < 4; j++)
            #pragma unroll
            for (int v = 0; v < 4; v++) acc[i][j][v] = 0.f;

    load_chunk(0); load_chunk(1); load_chunk(2);

    for (int i = 0; i < NC; i++) {
        cp_wait2();
        __syncthreads();
        uint32_t sb = base + (i % GSTAGES) * STAGE_BYTES;
        #pragma unroll
        for (int ks = 0; ks < 2; ks++) {
            uint32_t kb = ks * 32;   // bytes: 16 bf16
            uint32_t aH[4][4], aL[4][4], bH[4][2], bL[4][2];
            #pragma unroll
            for (int mi = 0; mi < 4; mi++) {
                uint32_t ad = sb + (uint32_t)(wm + mi*16) * 80 + kb + a_off;
                ldsm4(ad,           aH[mi][0], aH[mi][1], aH[mi][2], aH[mi][3]);
                ldsm4(ad + OPBYTES, aL[mi][0], aL[mi][1], aL[mi][2], aL[mi][3]);
            }
            #pragma unroll
            for (int nb = 0; nb < 2; nb++) {
                uint32_t bd = sb + 2*OPBYTES + (uint32_t)(wn + nb*16) * 80 + kb + b_off;
                ldsm4(bd,           bH[2*nb][0], bH[2*nb][1], bH[2*nb+1][0], bH[2*nb+1][1]);
                ldsm4(bd + OPBYTES, bL[2*nb][0], bL[2*nb][1], bL[2*nb+1][0], bL[2*nb+1][1]);
            }
            #pragma unroll
            for (int mi = 0; mi < 4; mi++)
                #pragma unroll
                for (int ni = 0; ni < 4; ni++) {
                    mma16816(acc[mi][ni], aH[mi], bH[ni]);
                    mma16816(acc[mi][ni], aH[mi], bL[ni]);
                    mma16816(acc[mi][ni], aL[mi], bH[ni]);
                }
        }
        __syncthreads();
        if (i + GSTAGES < NC) load_chunk(i + GSTAGES);
        else cp_commit();                 // keep group counting uniform for wait_group
    }

    // epilogue: c0,c1 at (row, col..col+1), c2,c3 at (row+8, ...)
    int erow = m0 + wm + (lid >> 2);
    int ecol = n0 + wn + (lid & 3) * 2;
    #pragma unroll
    for (int mi = 0; mi < 4; mi++) {
        #pragma unroll
        for (int ni = 0; ni < 4; ni++) {
            int r0 = erow + mi * 16;
            int cc = ecol + ni * 8;
            float2 v0 = make_float2(acc[mi][ni][0], acc[mi][ni][1]);
            float2 v1 = make_float2(acc[mi][ni][2], acc[mi][ni][3]);
            if (EPI == 2) {
                float2 q0 = *(const float2*)(res + (size_t)r0 * ldc + cc);
                float2 q1 = *(const float2*)(res + (size_t)(r0+8) * ldc + cc);
                v0.x += q0.x; v0.y += q0.y; v1.x += q1.x; v1.y += q1.y;
            }
            *(float2*)(C + (size_t)r0 * ldc + cc) = v0;
            *(float2*)(C + (size_t)(r0+8) * ldc + cc) = v1;
        }
    }
}

// ---------------- RMSNorm ----------------
__global__ void rmsnorm_kernel(const float* __restrict__ x, const float* __restrict__ w) {
    int row = blockIdx.x;
    int tid = threadIdx.x;
    const float4* xr = (const float4*)(x + (size_t)row * DMD);
    float4 v = xr[tid];
    float ss = v.x*v.x + v.y*v.y + v.z*v.z + v.w*v.w;
    __shared__ float red[8];
    #pragma unroll
    for (int o = 16; o > 0; o >>= 1) ss += __shfl_xor_sync(0xffffffffu, ss, o);
    if ((tid & 31) == 0) red[tid >> 5] = ss;
    __syncthreads();
    if (tid < 8) {
        float t = red[tid];
        #pragma unroll
        for (int o = 4; o > 0; o >>= 1) t += __shfl_xor_sync(0xffu, t, o, 8);
        if (tid == 0) red[0] = t;
    }
    __syncthreads();
    float scale = rsqrtf(red[0] * (1.0f / DMD) + 1e-5f);
    float4 wv = ((const float4*)w)[tid];
    float4 o4;
    o4.x = v.x * scale * wv.x;
    o4.y = v.y * scale * wv.y;
    o4.z = v.z * scale * wv.z;
    o4.w = v.w * scale * wv.w;
    ((float4*)(g_xn + (size_t)row * DMD))[tid] = o4;
}

// ---------------- fp32 TN SGEMM for dt: softplus epilogue ----------------
__global__ __launch_bounds__(256) void sgemm_dt(
    const float* __restrict__ A, int lda,
    const float* __restrict__ B, int ldb,
    float* __restrict__ C, int ldc, int K,
    const float* __restrict__ aux)
{
    __shared__ float As[16][128];
    __shared__ float Bs[16][128];
    int tid = threadIdx.x;
    int m0 = blockIdx.y * 128;
    int n0 = blockIdx.x * 128;
    int lr = tid >> 2;
    int lk = (tid & 3) << 2;
    const float* Ap = A + (size_t)(m0 + lr) * lda + lk;
    const float* Bp = B + (size_t)(n0 + lr) * ldb + lk;
    int trow = (tid >> 4) << 3;
    int tcol = (tid & 15) << 3;

    float acc[8][8];
    #pragma unroll
    for (int i = 0; i < 8; i++)
        #pragma unroll
        for (int j = 0; j < 8; j++) acc[i][j] = 0.f;

    for (int kt = 0; kt < K; kt += 16) {
        float4 a0 = *(const float4*)(Ap + kt);
        float4 a1 = *(const float4*)(Ap + (size_t)64 * lda + kt);
        float4 b0 = *(const float4*)(Bp + kt);
        float4 b1 = *(const float4*)(Bp + (size_t)64 * ldb + kt);
        __syncthreads();
        As[lk+0][lr] = a0.x; As[lk+1][lr] = a0.y; As[lk+2][lr] = a0.z; As[lk+3][lr] = a0.w;
        As[lk+0][lr+64] = a1.x; As[lk+1][lr+64] = a1.y; As[lk+2][lr+64] = a1.z; As[lk+3][lr+64] = a1.w;
        Bs[lk+0][lr] = b0.x; Bs[lk+1][lr] = b0.y; Bs[lk+2][lr] = b0.z; Bs[lk+3][lr] = b0.w;
        Bs[lk+0][lr+64] = b1.x; Bs[lk+1][lr+64] = b1.y; Bs[lk+2][lr+64] = b1.z; Bs[lk+3][lr+64] = b1.w;
        __syncthreads();
        #pragma unroll
        for (int kk = 0; kk < 16; kk++) {
            float ra[8], rb[8];
            *(float4*)(ra)   = *(const float4*)&As[kk][trow];
            *(float4*)(ra+4) = *(const float4*)&As[kk][trow+4];
            *(float4*)(rb)   = *(const float4*)&Bs[kk][tcol];
            *(float4*)(rb+4) = *(const float4*)&Bs[kk][tcol+4];
            #pragma unroll
            for (int i = 0; i < 8; i++)
                #pragma unroll
                for (int j = 0; j < 8; j++)
                    acc[i][j] += ra[i] * rb[j];
        }
    }

    #pragma unroll
    for (int i = 0; i < 8; i++) {
        int row = m0 + trow + i;
        #pragma unroll
        for (int j = 0; j < 8; j++) {
            int col = n0 + tcol + j;
            float v = acc[i][j] + aux[col];
            v = (v > 20.f) ? v : log1pf(expf(v));
            C[(size_t)row * ldc + col] = v;
        }
    }
}

// ---------------- causal depthwise conv (K=4) + SiLU ----------------
__global__ void conv_silu_kernel(const float* __restrict__ cw, const float* __restrict__ cb) {
    int idx = blockIdx.x * blockDim.x + threadIdx.x;
    const int ecnt = EE / 4;
    if (idx >= MM * ecnt) return;
    int e4 = idx % ecnt;
    int row = idx / ecnt;
    int l = row % LL;
    int e0 = e4 * 4;

    float wa[4][4];
    #pragma unroll
    for (int i = 0; i < 4; i++) {
        float4 wv = ((const float4*)cw)[e0 + i];
        wa[i][0] = wv.x; wa[i][1] = wv.y; wa[i][2] = wv.z; wa[i][3] = wv.w;
    }
    float4 acc = ((const float4*)cb)[e4];
    const float* up = g_xz + (size_t)row * (2*EE) + e0;
    #pragma unroll
    for (int j = 0; j < 4; j++) {
        int ls = l - 3 + j;
        if (ls >= 0) {
            float4 u = *(const float4*)(up + (ptrdiff_t)(j - 3) * (2*EE));
            acc.x += u.x * wa[0][j];
            acc.y += u.y * wa[1][j];
            acc.z += u.z * wa[2][j];
            acc.w += u.w * wa[3][j];
        }
    }
    float4 r;
    r.x = acc.x / (1.f + __expf(-acc.x));
    r.y = acc.y / (1.f + __expf(-acc.y));
    r.z = acc.z / (1.f + __expf(-acc.z));
    r.w = acc.w / (1.f + __expf(-acc.w));
    *(float4*)(g_uact + (size_t)row * EE + e0) = r;
}

// ---------------- x_proj split-K GEMM ----------------
__global__ __launch_bounds__(256) void xproj_gemm(const float* __restrict__ W) {
    __shared__ float As[32][132];
    __shared__ float Bs[32][100];
    int tid = threadIdx.x;
    int m0 = blockIdx.x * 128;
    int k0 = blockIdx.y * (EE / XKS);
    int trow = (tid >> 4) << 3;
    int tcol = (tid & 15) * 6;

    float acc[8][6];
    #pragma unroll
    for (int i = 0; i < 8; i++)
        #pragma unroll
        for (int j = 0; j < 6; j++) acc[i][j] = 0.f;

    for (int kt = 0; kt < EE / XKS; kt += 32) {
        int kb = k0 + kt;
        __syncthreads();
        #pragma unroll
        for (int i = 0; i < 4; i++) {
            int li = tid + i * 256;
            int row = li >> 3;
            int kq = (li & 7) << 2;
            float4 v = *(const float4*)(g_uact + (size_t)(m0 + row) * EE + kb + kq);
            As[kq+0][row] = v.x; As[kq+1][row] = v.y;
            As[kq+2][row] = v.z; As[kq+3][row] = v.w;
        }
        #pragma unroll
        for (int i = 0; i < 3; i++) {
            int li = tid + i * 256;
            int row = li >> 3;
            int kq = (li & 7) << 2;
            float4 v = *(const float4*)(W + (size_t)row * EE + kb + kq);
            Bs[kq+0][row] = v.x; Bs[kq+1][row] = v.y;
            Bs[kq+2][row] = v.z; Bs[kq+3][row] = v.w;
        }
        __syncthreads();
        #pragma unroll
        for (int kk = 0; kk < 32; kk++) {
            float ra[8], rb[6];
            *(float4*)(ra)   = *(const float4*)&As[kk][trow];
            *(float4*)(ra+4) = *(const float4*)&As[kk][trow+4];
            *(float2*)(rb)   = *(const float2*)&Bs[kk][tcol];
            *(float2*)(rb+2) = *(const float2*)&Bs[kk][tcol+2];
            *(float2*)(rb+4) = *(const float2*)&Bs[kk][tcol+4];
            #pragma unroll
            for (int i = 0; i < 8; i++)
                #pragma unroll
                for (int j = 0; j < 6; j++)
                    acc[i][j] += ra[i] * rb[j];
        }
    }

    float* outp = g_xpart + (size_t)blockIdx.y * MM * FDIM;
    #pragma unroll
    for (int i = 0; i < 8; i++)
        #pragma unroll
        for (int j = 0; j < 6; j++)
            outp[(size_t)(m0 + trow + i) * FDIM + tcol + j] = acc[i][j];
}

__global__ void xproj_reduce() {
    int idx = blockIdx.x * 256 + threadIdx.x;
    if (idx >= MM * FDIM) return;
    float s = 0.f;
    #pragma unroll
    for (int p = 0; p < XKS; p++) s += g_xpart[(size_t)p * MM * FDIM + idx];
    g_xdbl[idx] = s;
}

// ---------------- chunked selective scan ----------------
__global__ void scan_pass_kernel(const float* __restrict__ A_log,
                                 const float* __restrict__ Dvec,
                                 int pass) {
    int e = blockIdx.x * 128 + threadIdx.x;
    int chunk = blockIdx.y;
    int b = blockIdx.z;

    float A[NS];
    #pragma unroll
    for (int n = 0; n < NS; n++) A[n] = -expf(A_log[e * NS + n]);

    int hbase = ((b * NCH + chunk) * EE + e) * NS;
    float h[NS];
    if (pass) {
        #pragma unroll
        for (int n = 0; n < NS; n++) h[n] = g_hinit[hbase + n];
    } else {
        #pragma unroll
        for (int n = 0; n < NS; n++) h[n] = 0.f;
    }
    float Dval = pass ? Dvec[e] : 0.f;
    float sdt = 0.f;

    __shared__ float sB[2][NS], sC[2][NS];

    for (int i = 0; i < CLEN; i++) {
        int l = chunk * CLEN + i;
        int row = b * LL + l;
        int s = i & 1;
        if (threadIdx.x < 2 * NS) {
            float v = g_xdbl[(size_t)row * FDIM + RR + threadIdx.x];
            if (threadIdx.x < NS) sB[s][threadIdx.x] = v;
            else                  sC[s][threadIdx.x - NS] = v;
        }
        __syncthreads();
        float dtv = g_dt[(size_t)row * EE + e];
        float uv  = g_uact[(size_t)row * EE + e];
        sdt += dtv;
        float du = dtv * uv;
        if (pass) {
            float y = 0.f;
            #pragma unroll
            for (int n = 0; n < NS; n++) {
                float dA = __expf(dtv * A[n]);
                h[n] = h[n] * dA + du * sB[s][n];
                y += h[n] * sC[s][n];
            }
            float z = g_xz[(size_t)row * (2*EE) + EE + e];
            float sig = 1.f / (1.f + __expf(-z));
            g_ygate[(size_t)row * EE + e] = (y + uv * Dval) * (z * sig);
        } else {
            #pragma unroll
            for (int n = 0; n < NS; n++) {
                float dA = __expf(dtv * A[n]);
                h[n] = h[n] * dA + du * sB[s][n];
            }
        }
    }
    if (!pass) {
        #pragma unroll
        for (int n = 0; n < NS; n++) g_hend[hbase + n] = h[n];
        g_sumdt[(b * NCH + chunk) * EE + e] = sdt;
    }
}

__global__ void scan_combine_kernel(const float* __restrict__ A_log) {
    int idx = blockIdx.x * blockDim.x + threadIdx.x;
    if (idx >= BB * EE) return;
    int e = idx % EE;
    int b = idx / EE;
    float A[NS];
    #pragma unroll
    for (int n = 0; n < NS; n++) A[n] = -expf(A_log[e * NS + n]);
    float H[NS];
    #pragma unroll
    for (int n = 0; n < NS; n++) H[n] = 0.f;
    for (int c = 0; c < NCH; c++) {
        int base = ((b * NCH + c) * EE + e) * NS;
        #pragma unroll
        for (int n = 0; n < NS; n++) g_hinit[base + n] = H[n];
        float s = g_sumdt[(b * NCH + c) * EE + e];
        #pragma unroll
        for (int n = 0; n < NS; n++)
            H[n] = g_hend[base + n] + __expf(A[n] * s) * H[n];
    }
}

// ---------------- launch ----------------
extern "C" void kernel_launch(void* const* d_in, const int* in_sizes, int n_in,
                              void* d_out, int out_size) {
    const float* x         = (const float*)d_in[0];
    const float* norm_w    = (const float*)d_in[1];
    const float* in_proj_w = (const float*)d_in[2];
    const float* conv_w    = (const float*)d_in[3];
    const float* conv_b    = (const float*)d_in[4];
    const float* x_proj_w  = (const float*)d_in[5];
    const float* dt_proj_w = (const float*)d_in[6];
    const float* dt_proj_b = (const float*)d_in[7];
    const float* A_log     = (const float*)d_in[8];
    const float* Dvec      = (const float*)d_in[9];
    const float* out_proj_w= (const float*)d_in[10];
    float* out = (float*)d_out;

    float *p_xn, *p_xz, *p_xdbl, *p_dt, *p_ygate;
    cudaGetSymbolAddress((void**)&p_xn, g_xn);
    cudaGetSymbolAddress((void**)&p_xz, g_xz);
    cudaGetSymbolAddress((void**)&p_xdbl, g_xdbl);
    cudaGetSymbolAddress((void**)&p_dt, g_dt);
    cudaGetSymbolAddress((void**)&p_ygate, g_ygate);
    __nv_bfloat16 *p_xnh, *p_xnl, *p_w1h, *p_w1l, *p_ygh, *p_ygl, *p_w2h, *p_w2l;
    cudaGetSymbolAddress((void**)&p_xnh, g_xn_h);
    cudaGetSymbolAddress((void**)&p_xnl, g_xn_l);
    cudaGetSymbolAddress((void**)&p_w1h, g_w1_h);
    cudaGetSymbolAddress((void**)&p_w1l, g_w1_l);
    cudaGetSymbolAddress((void**)&p_ygh, g_yg_h);
    cudaGetSymbolAddress((void**)&p_ygl, g_yg_l);
    cudaGetSymbolAddress((void**)&p_w2h, g_w2_h);
    cudaGetSymbolAddress((void**)&p_w2l, g_w2_l);

    cudaFuncSetAttribute(hmma_gemm<DMD,0>, cudaFuncAttributeMaxDynamicSharedMemorySize, DSMEM);
    cudaFuncSetAttribute(hmma_gemm<EE,2>,  cudaFuncAttributeMaxDynamicSharedMemorySize, DSMEM);

    // 1. RMSNorm
    rmsnorm_kernel<<<MM, 256>>>(x, norm_w);
    // 2. split xn and in_proj_w to bf16 hi/lo
    cvt_hilo<<<(MM*DMD/4 + 255)/256, 256>>>(p_xn, p_xnh, p_xnl, MM*DMD/4);
    cvt_hilo<<<(2*EE*DMD/4 + 255)/256, 256>>>(in_proj_w, p_w1h, p_w1l, 2*EE*DMD/4);
    // 3. in_proj via HMMA: xz[4096,4096] = xn[4096,1024] @ W1[4096,1024]^T
    hmma_gemm<DMD,0><<<dim3(2*EE/128, MM/128), 256, DSMEM>>>(
        p_xnh, p_xnl, p_w1h, p_w1l, p_xz, 2*EE, nullptr);
    // 4. causal depthwise conv + SiLU -> u_act
    conv_silu_kernel<<<(MM * (EE/4)) / 256, 256>>>(conv_w, conv_b);
    // 5. x_proj -> x_dbl[4096, 96]
    xproj_gemm<<<dim3(MM/128, XKS), 256>>>(x_proj_w);
    xproj_reduce<<<(MM*FDIM)/256, 256>>>();
    // 6. dt = softplus(dt_low @ dtW^T + b)
    sgemm_dt<<<dim3(EE/128, MM/128), 256>>>(p_xdbl, FDIM, dt_proj_w, RR, p_dt, EE, RR, dt_proj_b);
    // 7. chunked selective scan + fused gate
    scan_pass_kernel<<<dim3(EE/128, NCH, BB), 128>>>(A_log, Dvec, 0);
    scan_combine_kernel<<<(BB*EE)/256, 256>>>(A_log);
    scan_pass_kernel<<<dim3(EE/128, NCH, BB), 128>>>(A_log, Dvec, 1);
    // 8. split ygate and out_proj_w to bf16 hi/lo
    cvt_hilo<<<(MM*EE/4 + 255)/256, 256>>>(p_ygate, p_ygh, p_ygl, MM*EE/4);
    cvt_hilo<<<(DMD*EE/4 + 255)/256, 256>>>(out_proj_w, p_w2h, p_w2l, DMD*EE/4);
    // 9. out_proj + residual via HMMA
    hmma_gemm<EE,2><<<dim3(DMD/128, MM/128), 256, DSMEM>>>(
        p_ygh, p_ygl, p_w2h, p_w2l, out, DMD, x);
}

// round 8
// speedup vs baseline: 2.4177x; 1.0735x over previous
#include <cuda_runtime.h>
#include <cuda_bf16.h>
#include <math.h>
#include <stdint.h>

#define BB 2
#define LL 2048
#define DMD 1024
#define EE 2048
#define NS 16
#define RR 64
#define MM (BB*LL)          // 4096
#define NCH 16
#define CLEN (LL/NCH)       // 128
#define FDIM (RR + 2*NS)    // 96
#define XKS 4               // split-K factor for x_proj

// HMMA GEMM tiling
#define LDSROW 40           // bf16 elems per smem row (32 data + 8 pad) -> 80B stride
#define OPBYTES (128*LDSROW*2)   // 10240 per operand per stage
#define STAGE_BYTES (4*OPBYTES)  // Ah | Al | Bh | Bl
#define GSTAGES 2
#define DSMEM (GSTAGES*STAGE_BYTES)   // 81920 -> 2 CTAs/SM

// ---------------- scratch (static device globals; no runtime alloc) ----------------
__device__ float g_xz[MM*2*EE];
__device__ float g_uact[MM*EE];
__device__ float g_xdbl[MM*FDIM];
__device__ float g_xpart[XKS*MM*FDIM];
__device__ float g_dt[MM*EE];
__device__ float g_hend[BB*NCH*EE*NS];
__device__ float g_hinit[BB*NCH*EE*NS];
__device__ float g_sumdt[BB*NCH*EE];
// bf16 hi/lo split operands (16B-aligned for cp.async/float4)
__device__ __align__(256) __nv_bfloat16 g_xn_h[MM*DMD];
__device__ __align__(256) __nv_bfloat16 g_xn_l[MM*DMD];
__device__ __align__(256) __nv_bfloat16 g_w1_h[2*EE*DMD];
__device__ __align__(256) __nv_bfloat16 g_w1_l[2*EE*DMD];
__device__ __align__(256) __nv_bfloat16 g_yg_h[MM*EE];
__device__ __align__(256) __nv_bfloat16 g_yg_l[MM*EE];
__device__ __align__(256) __nv_bfloat16 g_w2_h[DMD*EE];
__device__ __align__(256) __nv_bfloat16 g_w2_l[DMD*EE];

// ---------------- PTX helpers (sm_80-era ISA only; no tcgen05) ----------------
__device__ __forceinline__ uint32_t smem_u32(const void* p) {
    uint32_t a;
    asm("{ .reg .u64 t; cvta.to.shared.u64 t, %1; cvt.u32.u64 %0, t; }" : "=r"(a) : "l"(p));
    return a;
}
__device__ __forceinline__ void ldgsts16(uint32_t s, const void* g) {
    asm volatile("cp.async.cg.shared.global [%0], [%1], 16;" :: "r"(s), "l"(g));
}
__device__ __forceinline__ void cp_commit() {
    asm volatile("cp.async.commit_group;" ::: "memory");
}
__device__ __forceinline__ void cp_wait1() {
    asm volatile("cp.async.wait_group 1;" ::: "memory");
}
__device__ __forceinline__ void ldsm4(uint32_t a, uint32_t& r0, uint32_t& r1,
                                      uint32_t& r2, uint32_t& r3) {
    asm volatile("ldmatrix.sync.aligned.m8n8.x4.shared.b16 {%0,%1,%2,%3}, [%4];"
        : "=r"(r0), "=r"(r1), "=r"(r2), "=r"(r3) : "r"(a));
}
__device__ __forceinline__ void mma16816(float* c, const uint32_t* a, const uint32_t* b) {
    asm volatile(
        "mma.sync.aligned.m16n8k16.row.col.f32.bf16.bf16.f32 "
        "{%0,%1,%2,%3}, {%4,%5,%6,%7}, {%8,%9}, {%0,%1,%2,%3};"
        : "+f"(c[0]), "+f"(c[1]), "+f"(c[2]), "+f"(c[3])
        : "r"(a[0]), "r"(a[1]), "r"(a[2]), "r"(a[3]), "r"(b[0]), "r"(b[1]));
}
__device__ __forceinline__ void split_hilo(float v, __nv_bfloat16& h, __nv_bfloat16& l) {
    h = __float2bfloat16_rn(v);
    l = __float2bfloat16_rn(v - __bfloat162float(h));
}

// ---------------- fp32 -> bf16 hi/lo split (weights only) ----------------
__global__ void cvt_hilo(const float* __restrict__ src,
                         __nv_bfloat16* __restrict__ h,
                         __nv_bfloat16* __restrict__ l, int n4) {
    int i = blockIdx.x * 256 + threadIdx.x;
    if (i >= n4) return;
    float4 v = ((const float4*)src)[i];
    __nv_bfloat16 h0, h1, h2, h3, l0, l1, l2, l3;
    split_hilo(v.x, h0, l0); split_hilo(v.y, h1, l1);
    split_hilo(v.z, h2, l2); split_hilo(v.w, h3, l3);
    ((__nv_bfloat162*)h)[2*i]   = __nv_bfloat162(h0, h1);
    ((__nv_bfloat162*)h)[2*i+1] = __nv_bfloat162(h2, h3);
    ((__nv_bfloat162*)l)[2*i]   = __nv_bfloat162(l0, l1);
    ((__nv_bfloat162*)l)[2*i+1] = __nv_bfloat162(l2, l3);
}

// ---------------- split-bf16 HMMA GEMM: C[M,N] = A[M,K] * B[N,K]^T ----------------
// 128x128 CTA tile, 8 warps (2x4), 64x32 per warp, BK=32, 2-stage cp.async,
// 2 CTAs/SM for cross-CTA latency hiding.
// D = Ah*Bh + Ah*Bl + Al*Bh accumulated in fp32. EPI: 0=store, 2=+res.
template <int KEL, int EPI>
__global__ void __launch_bounds__(256, 2) hmma_gemm(
    const __nv_bfloat16* __restrict__ Ah, const __nv_bfloat16* __restrict__ Al,
    const __nv_bfloat16* __restrict__ Bh, const __nv_bfloat16* __restrict__ Bl,
    float* __restrict__ C, int ldc, const float* __restrict__ res)
{
    constexpr int NC = KEL / 32;           // k-chunks
    extern __shared__ __align__(128) char dsm[];
    uint32_t base = smem_u32(dsm);

    int tid = threadIdx.x, lid = tid & 31, wid = tid >> 5;
    int wm = (wid & 1) * 64;               // warp row offset
    int wn = (wid >> 1) * 32;              // warp col offset
    int m0 = blockIdx.y * 128, n0 = blockIdx.x * 128;

    // cp.async geometry: thread -> (row, 2 of 4 16B segs)
    int grow = tid >> 1;
    int gseg = (tid & 1) * 2;
    const char* pAh = (const char*)(Ah + (size_t)m0 * KEL);
    const char* pAl = (const char*)(Al + (size_t)m0 * KEL);
    const char* pBh = (const char*)(Bh + (size_t)n0 * KEL);
    const char* pBl = (const char*)(Bl + (size_t)n0 * KEL);

    auto load_chunk = [&](int c) {
        uint32_t sb = base + (c % GSTAGES) * STAGE_BYTES;
        #pragma unroll
        for (int s2 = 0; s2 < 2; s2++) {
            int seg = gseg + s2;
            uint32_t so = grow * 80 + seg * 16;
            size_t go = (size_t)grow * (KEL * 2) + (size_t)c * 64 + seg * 16;
            ldgsts16(sb +             so, pAh + go);
            ldgsts16(sb + OPBYTES   + so, pAl + go);
            ldgsts16(sb + 2*OPBYTES + so, pBh + go);
            ldgsts16(sb + 3*OPBYTES + so, pBl + go);
        }
        cp_commit();
    };

    // per-lane ldmatrix offsets
    int quad = lid >> 3, r8 = lid & 7;
    uint32_t a_off = (uint32_t)((quad & 1) * 8 + r8) * 80 + (uint32_t)(quad >> 1) * 16;
    uint32_t b_off = (uint32_t)((quad >> 1) * 8 + r8) * 80 + (uint32_t)(quad & 1) * 16;

    float acc[4][4][4];
    #pragma unroll
    for (int i = 0; i < 4; i++)
        #pragma unroll
        for (int j = 0; j < 4; j++)
            #pragma unroll
            for (int v = 0; v < 4; v++) acc[i][j][v] = 0.f;

    load_chunk(0); load_chunk(1);

    for (int i = 0; i < NC; i++) {
        cp_wait1();
        __syncthreads();
        uint32_t sb = base + (i % GSTAGES) * STAGE_BYTES;
        #pragma unroll
        for (int ks = 0; ks < 2; ks++) {
            uint32_t kb = ks * 32;   // bytes: 16 bf16
            uint32_t aH[4][4], aL[4][4], bH[4][2], bL[4][2];
            #pragma unroll
            for (int mi = 0; mi < 4; mi++) {
                uint32_t ad = sb + (uint32_t)(wm + mi*16) * 80 + kb + a_off;
                ldsm4(ad,           aH[mi][0], aH[mi][1], aH[mi][2], aH[mi][3]);
                ldsm4(ad + OPBYTES, aL[mi][0], aL[mi][1], aL[mi][2], aL[mi][3]);
            }
            #pragma unroll
            for (int nb = 0; nb < 2; nb++) {
                uint32_t bd = sb + 2*OPBYTES + (uint32_t)(wn + nb*16) * 80 + kb + b_off;
                ldsm4(bd,           bH[2*nb][0], bH[2*nb][1], bH[2*nb+1][0], bH[2*nb+1][1]);
                ldsm4(bd + OPBYTES, bL[2*nb][0], bL[2*nb][1], bL[2*nb+1][0], bL[2*nb+1][1]);
            }
            #pragma unroll
            for (int mi = 0; mi < 4; mi++)
                #pragma unroll
                for (int ni = 0; ni < 4; ni++) {
                    mma16816(acc[mi][ni], aH[mi], bH[ni]);
                    mma16816(acc[mi][ni], aH[mi], bL[ni]);
                    mma16816(acc[mi][ni], aL[mi], bH[ni]);
                }
        }
        __syncthreads();
        if (i + GSTAGES < NC) load_chunk(i + GSTAGES);
        else cp_commit();                 // keep group counting uniform for wait_group
    }

    // epilogue: c0,c1 at (row, col..col+1), c2,c3 at (row+8, ...)
    int erow = m0 + wm + (lid >> 2);
    int ecol = n0 + wn + (lid & 3) * 2;
    #pragma unroll
    for (int mi = 0; mi < 4; mi++) {
        #pragma unroll
        for (int ni = 0; ni < 4; ni++) {
            int r0 = erow + mi * 16;
            int cc = ecol + ni * 8;
            float2 v0 = make_float2(acc[mi][ni][0], acc[mi][ni][1]);
            float2 v1 = make_float2(acc[mi][ni][2], acc[mi][ni][3]);
            if (EPI == 2) {
                float2 q0 = *(const float2*)(res + (size_t)r0 * ldc + cc);
                float2 q1 = *(const float2*)(res + (size_t)(r0+8) * ldc + cc);
                v0.x += q0.x; v0.y += q0.y; v1.x += q1.x; v1.y += q1.y;
            }
            *(float2*)(C + (size_t)r0 * ldc + cc) = v0;
            *(float2*)(C + (size_t)(r0+8) * ldc + cc) = v1;
        }
    }
}

// ---------------- RMSNorm (writes bf16 hi/lo directly) ----------------
__global__ void rmsnorm_kernel(const float* __restrict__ x, const float* __restrict__ w) {
    int row = blockIdx.x;
    int tid = threadIdx.x;
    const float4* xr = (const float4*)(x + (size_t)row * DMD);
    float4 v = xr[tid];
    float ss = v.x*v.x + v.y*v.y + v.z*v.z + v.w*v.w;
    __shared__ float red[8];
    #pragma unroll
    for (int o = 16; o > 0; o >>= 1) ss += __shfl_xor_sync(0xffffffffu, ss, o);
    if ((tid & 31) == 0) red[tid >> 5] = ss;
    __syncthreads();
    if (tid < 8) {
        float t = red[tid];
        #pragma unroll
        for (int o = 4; o > 0; o >>= 1) t += __shfl_xor_sync(0xffu, t, o, 8);
        if (tid == 0) red[0] = t;
    }
    __syncthreads();
    float scale = rsqrtf(red[0] * (1.0f / DMD) + 1e-5f);
    float4 wv = ((const float4*)w)[tid];
    float4 o4;
    o4.x = v.x * scale * wv.x;
    o4.y = v.y * scale * wv.y;
    o4.z = v.z * scale * wv.z;
    o4.w = v.w * scale * wv.w;
    __nv_bfloat16 h0,h1,h2,h3,l0,l1,l2,l3;
    split_hilo(o4.x, h0, l0); split_hilo(o4.y, h1, l1);
    split_hilo(o4.z, h2, l2); split_hilo(o4.w, h3, l3);
    size_t idx2 = (size_t)row * (DMD/2) + tid * 2;
    ((__nv_bfloat162*)g_xn_h)[idx2]   = __nv_bfloat162(h0, h1);
    ((__nv_bfloat162*)g_xn_h)[idx2+1] = __nv_bfloat162(h2, h3);
    ((__nv_bfloat162*)g_xn_l)[idx2]   = __nv_bfloat162(l0, l1);
    ((__nv_bfloat162*)g_xn_l)[idx2+1] = __nv_bfloat162(l2, l3);
}

// ---------------- fp32 TN SGEMM for dt: softplus epilogue ----------------
__global__ __launch_bounds__(256) void sgemm_dt(
    const float* __restrict__ A, int lda,
    const float* __restrict__ B, int ldb,
    float* __restrict__ C, int ldc, int K,
    const float* __restrict__ aux)
{
    __shared__ float As[16][128];
    __shared__ float Bs[16][128];
    int tid = threadIdx.x;
    int m0 = blockIdx.y * 128;
    int n0 = blockIdx.x * 128;
    int lr = tid >> 2;
    int lk = (tid & 3) << 2;
    const float* Ap = A + (size_t)(m0 + lr) * lda + lk;
    const float* Bp = B + (size_t)(n0 + lr) * ldb + lk;
    int trow = (tid >> 4) << 3;
    int tcol = (tid & 15) << 3;

    float acc[8][8];
    #pragma unroll
    for (int i = 0; i < 8; i++)
        #pragma unroll
        for (int j = 0; j < 8; j++) acc[i][j] = 0.f;

    for (int kt = 0; kt < K; kt += 16) {
        float4 a0 = *(const float4*)(Ap + kt);
        float4 a1 = *(const float4*)(Ap + (size_t)64 * lda + kt);
        float4 b0 = *(const float4*)(Bp + kt);
        float4 b1 = *(const float4*)(Bp + (size_t)64 * ldb + kt);
        __syncthreads();
        As[lk+0][lr] = a0.x; As[lk+1][lr] = a0.y; As[lk+2][lr] = a0.z; As[lk+3][lr] = a0.w;
        As[lk+0][lr+64] = a1.x; As[lk+1][lr+64] = a1.y; As[lk+2][lr+64] = a1.z; As[lk+3][lr+64] = a1.w;
        Bs[lk+0][lr] = b0.x; Bs[lk+1][lr] = b0.y; Bs[lk+2][lr] = b0.z; Bs[lk+3][lr] = b0.w;
        Bs[lk+0][lr+64] = b1.x; Bs[lk+1][lr+64] = b1.y; Bs[lk+2][lr+64] = b1.z; Bs[lk+3][lr+64] = b1.w;
        __syncthreads();
        #pragma unroll
        for (int kk = 0; kk < 16; kk++) {
            float ra[8], rb[8];
            *(float4*)(ra)   = *(const float4*)&As[kk][trow];
            *(float4*)(ra+4) = *(const float4*)&As[kk][trow+4];
            *(float4*)(rb)   = *(const float4*)&Bs[kk][tcol];
            *(float4*)(rb+4) = *(const float4*)&Bs[kk][tcol+4];
            #pragma unroll
            for (int i = 0; i < 8; i++)
                #pragma unroll
                for (int j = 0; j < 8; j++)
                    acc[i][j] += ra[i] * rb[j];
        }
    }

    #pragma unroll
    for (int i = 0; i < 8; i++) {
        int row = m0 + trow + i;
        #pragma unroll
        for (int j = 0; j < 8; j++) {
            int col = n0 + tcol + j;
            float v = acc[i][j] + aux[col];
            v = (v > 20.f) ? v : log1pf(expf(v));
            C[(size_t)row * ldc + col] = v;
        }
    }
}

// ---------------- causal depthwise conv (K=4) + SiLU ----------------
__global__ void conv_silu_kernel(const float* __restrict__ cw, const float* __restrict__ cb) {
    int idx = blockIdx.x * blockDim.x + threadIdx.x;
    const int ecnt = EE / 4;
    if (idx >= MM * ecnt) return;
    int e4 = idx % ecnt;
    int row = idx / ecnt;
    int l = row % LL;
    int e0 = e4 * 4;

    float wa[4][4];
    #pragma unroll
    for (int i = 0; i < 4; i++) {
        float4 wv = ((const float4*)cw)[e0 + i];
        wa[i][0] = wv.x; wa[i][1] = wv.y; wa[i][2] = wv.z; wa[i][3] = wv.w;
    }
    float4 acc = ((const float4*)cb)[e4];
    const float* up = g_xz + (size_t)row * (2*EE) + e0;
    #pragma unroll
    for (int j = 0; j < 4; j++) {
        int ls = l - 3 + j;
        if (ls >= 0) {
            float4 u = *(const float4*)(up + (ptrdiff_t)(j - 3) * (2*EE));
            acc.x += u.x * wa[0][j];
            acc.y += u.y * wa[1][j];
            acc.z += u.z * wa[2][j];
            acc.w += u.w * wa[3][j];
        }
    }
    float4 r;
    r.x = acc.x / (1.f + __expf(-acc.x));
    r.y = acc.y / (1.f + __expf(-acc.y));
    r.z = acc.z / (1.f + __expf(-acc.z));
    r.w = acc.w / (1.f + __expf(-acc.w));
    *(float4*)(g_uact + (size_t)row * EE + e0) = r;
}

// ---------------- x_proj split-K GEMM ----------------
__global__ __launch_bounds__(256) void xproj_gemm(const float* __restrict__ W) {
    __shared__ float As[32][132];
    __shared__ float Bs[32][100];
    int tid = threadIdx.x;
    int m0 = blockIdx.x * 128;
    int k0 = blockIdx.y * (EE / XKS);
    int trow = (tid >> 4) << 3;
    int tcol = (tid & 15) * 6;

    float acc[8][6];
    #pragma unroll
    for (int i = 0; i < 8; i++)
        #pragma unroll
        for (int j = 0; j < 6; j++) acc[i][j] = 0.f;

    for (int kt = 0; kt < EE / XKS; kt += 32) {
        int kb = k0 + kt;
        __syncthreads();
        #pragma unroll
        for (int i = 0; i < 4; i++) {
            int li = tid + i * 256;
            int row = li >> 3;
            int kq = (li & 7) << 2;
            float4 v = *(const float4*)(g_uact + (size_t)(m0 + row) * EE + kb + kq);
            As[kq+0][row] = v.x; As[kq+1][row] = v.y;
            As[kq+2][row] = v.z; As[kq+3][row] = v.w;
        }
        #pragma unroll
        for (int i = 0; i < 3; i++) {
            int li = tid + i * 256;
            int row = li >> 3;
            int kq = (li & 7) << 2;
            float4 v = *(const float4*)(W + (size_t)row * EE + kb + kq);
            Bs[kq+0][row] = v.x; Bs[kq+1][row] = v.y;
            Bs[kq+2][row] = v.z; Bs[kq+3][row] = v.w;
        }
        __syncthreads();
        #pragma unroll
        for (int kk = 0; kk < 32; kk++) {
            float ra[8], rb[6];
            *(float4*)(ra)   = *(const float4*)&As[kk][trow];
            *(float4*)(ra+4) = *(const float4*)&As[kk][trow+4];
            *(float2*)(rb)   = *(const float2*)&Bs[kk][tcol];
            *(float2*)(rb+2) = *(const float2*)&Bs[kk][tcol+2];
            *(float2*)(rb+4) = *(const float2*)&Bs[kk][tcol+4];
            #pragma unroll
            for (int i = 0; i < 8; i++)
                #pragma unroll
                for (int j = 0; j < 6; j++)
                    acc[i][j] += ra[i] * rb[j];
        }
    }

    float* outp = g_xpart + (size_t)blockIdx.y * MM * FDIM;
    #pragma unroll
    for (int i = 0; i < 8; i++)
        #pragma unroll
        for (int j = 0; j < 6; j++)
            outp[(size_t)(m0 + trow + i) * FDIM + tcol + j] = acc[i][j];
}

__global__ void xproj_reduce() {
    int idx = blockIdx.x * 256 + threadIdx.x;
    if (idx >= MM * FDIM) return;
    float s = 0.f;
    #pragma unroll
    for (int p = 0; p < XKS; p++) s += g_xpart[(size_t)p * MM * FDIM + idx];
    g_xdbl[idx] = s;
}

// ---------------- chunked selective scan ----------------
// pass 0: local scan, record h_end + sum(dt). pass 1: rescan + gate, write bf16 hi/lo.
__global__ void scan_pass_kernel(const float* __restrict__ A_log,
                                 const float* __restrict__ Dvec,
                                 int pass) {
    int e = blockIdx.x * 128 + threadIdx.x;
    int chunk = blockIdx.y;
    int b = blockIdx.z;

    float A[NS];
    #pragma unroll
    for (int n = 0; n < NS; n++) A[n] = -expf(A_log[e * NS + n]);

    int hbase = ((b * NCH + chunk) * EE + e) * NS;
    float h[NS];
    if (pass) {
        #pragma unroll
        for (int n = 0; n < NS; n++) h[n] = g_hinit[hbase + n];
    } else {
        #pragma unroll
        for (int n = 0; n < NS; n++) h[n] = 0.f;
    }
    float Dval = pass ? Dvec[e] : 0.f;
    float sdt = 0.f;

    __shared__ float sB[2][NS], sC[2][NS];

    for (int i = 0; i < CLEN; i++) {
        int l = chunk * CLEN + i;
        int row = b * LL + l;
        int s = i & 1;
        if (threadIdx.x < 2 * NS) {
            float v = g_xdbl[(size_t)row * FDIM + RR + threadIdx.x];
            if (threadIdx.x < NS) sB[s][threadIdx.x] = v;
            else                  sC[s][threadIdx.x - NS] = v;
        }
        __syncthreads();
        float dtv = g_dt[(size_t)row * EE + e];
        float uv  = g_uact[(size_t)row * EE + e];
        sdt += dtv;
        float du = dtv * uv;
        if (pass) {
            float y = 0.f;
            #pragma unroll
            for (int n = 0; n < NS; n++) {
                float dA = __expf(dtv * A[n]);
                h[n] = h[n] * dA + du * sB[s][n];
                y += h[n] * sC[s][n];
            }
            float z = g_xz[(size_t)row * (2*EE) + EE + e];
            float sig = 1.f / (1.f + __expf(-z));
            float val = (y + uv * Dval) * (z * sig);
            __nv_bfloat16 vh, vl;
            split_hilo(val, vh, vl);
            g_yg_h[(size_t)row * EE + e] = vh;
            g_yg_l[(size_t)row * EE + e] = vl;
        } else {
            #pragma unroll
            for (int n = 0; n < NS; n++) {
                float dA = __expf(dtv * A[n]);
                h[n] = h[n] * dA + du * sB[s][n];
            }
        }
    }
    if (!pass) {
        #pragma unroll
        for (int n = 0; n < NS; n++) g_hend[hbase + n] = h[n];
        g_sumdt[(b * NCH + chunk) * EE + e] = sdt;
    }
}

__global__ void scan_combine_kernel(const float* __restrict__ A_log) {
    int idx = blockIdx.x * blockDim.x + threadIdx.x;
    if (idx >= BB * EE) return;
    int e = idx % EE;
    int b = idx / EE;
    float A[NS];
    #pragma unroll
    for (int n = 0; n < NS; n++) A[n] = -expf(A_log[e * NS + n]);
    float H[NS];
    #pragma unroll
    for (int n = 0; n < NS; n++) H[n] = 0.f;
    for (int c = 0; c < NCH; c++) {
        int base = ((b * NCH + c) * EE + e) * NS;
        #pragma unroll
        for (int n = 0; n < NS; n++) g_hinit[base + n] = H[n];
        float s = g_sumdt[(b * NCH + c) * EE + e];
        #pragma unroll
        for (int n = 0; n < NS; n++)
            H[n] = g_hend[base + n] + __expf(A[n] * s) * H[n];
    }
}

// ---------------- launch ----------------
extern "C" void kernel_launch(void* const* d_in, const int* in_sizes, int n_in,
                              void* d_out, int out_size) {
    const float* x         = (const float*)d_in[0];
    const float* norm_w    = (const float*)d_in[1];
    const float* in_proj_w = (const float*)d_in[2];
    const float* conv_w    = (const float*)d_in[3];
    const float* conv_b    = (const float*)d_in[4];
    const float* x_proj_w  = (const float*)d_in[5];
    const float* dt_proj_w = (const float*)d_in[6];
    const float* dt_proj_b = (const float*)d_in[7];
    const float* A_log     = (const float*)d_in[8];
    const float* Dvec      = (const float*)d_in[9];
    const float* out_proj_w= (const float*)d_in[10];
    float* out = (float*)d_out;

    float *p_xz, *p_xdbl, *p_dt;
    cudaGetSymbolAddress((void**)&p_xz, g_xz);
    cudaGetSymbolAddress((void**)&p_xdbl, g_xdbl);
    cudaGetSymbolAddress((void**)&p_dt, g_dt);
    __nv_bfloat16 *p_xnh, *p_xnl, *p_w1h, *p_w1l, *p_ygh, *p_ygl, *p_w2h, *p_w2l;
    cudaGetSymbolAddress((void**)&p_xnh, g_xn_h);
    cudaGetSymbolAddress((void**)&p_xnl, g_xn_l);
    cudaGetSymbolAddress((void**)&p_w1h, g_w1_h);
    cudaGetSymbolAddress((void**)&p_w1l, g_w1_l);
    cudaGetSymbolAddress((void**)&p_ygh, g_yg_h);
    cudaGetSymbolAddress((void**)&p_ygl, g_yg_l);
    cudaGetSymbolAddress((void**)&p_w2h, g_w2_h);
    cudaGetSymbolAddress((void**)&p_w2l, g_w2_l);

    cudaFuncSetAttribute(hmma_gemm<DMD,0>, cudaFuncAttributeMaxDynamicSharedMemorySize, DSMEM);
    cudaFuncSetAttribute(hmma_gemm<EE,2>,  cudaFuncAttributeMaxDynamicSharedMemorySize, DSMEM);

    // 1. RMSNorm -> bf16 hi/lo directly
    rmsnorm_kernel<<<MM, 256>>>(x, norm_w);
    // 2. split in_proj_w to bf16 hi/lo
    cvt_hilo<<<(2*EE*DMD/4 + 255)/256, 256>>>(in_proj_w, p_w1h, p_w1l, 2*EE*DMD/4);
    // 3. in_proj via HMMA: xz[4096,4096] = xn[4096,1024] @ W1[4096,1024]^T
    hmma_gemm<DMD,0><<<dim3(2*EE/128, MM/128), 256, DSMEM>>>(
        p_xnh, p_xnl, p_w1h, p_w1l, p_xz, 2*EE, nullptr);
    // 4. causal depthwise conv + SiLU -> u_act
    conv_silu_kernel<<<(MM * (EE/4)) / 256, 256>>>(conv_w, conv_b);
    // 5. x_proj -> x_dbl[4096, 96]
    xproj_gemm<<<dim3(MM/128, XKS), 256>>>(x_proj_w);
    xproj_reduce<<<(MM*FDIM)/256, 256>>>();
    // 6. dt = softplus(dt_low @ dtW^T + b)
    sgemm_dt<<<dim3(EE/128, MM/128), 256>>>(p_xdbl, FDIM, dt_proj_w, RR, p_dt, EE, RR, dt_proj_b);
    // 7. chunked selective scan + fused gate (pass1 writes bf16 hi/lo)
    scan_pass_kernel<<<dim3(EE/128, NCH, BB), 128>>>(A_log, Dvec, 0);
    scan_combine_kernel<<<(BB*EE)/256, 256>>>(A_log);
    scan_pass_kernel<<<dim3(EE/128, NCH, BB), 128>>>(A_log, Dvec, 1);
    // 8. split out_proj_w to bf16 hi/lo
    cvt_hilo<<<(DMD*EE/4 + 255)/256, 256>>>(out_proj_w, p_w2h, p_w2l, DMD*EE/4);
    // 9. out_proj + residual via HMMA
    hmma_gemm<EE,2><<<dim3(DMD/128, MM/128), 256, DSMEM>>>(
        p_ygh, p_ygl, p_w2h, p_w2l, out, DMD, x);
}